// round 2
// baseline (speedup 1.0000x reference)
#include <cuda_runtime.h>
#include <cstddef>

// Problem constants (fixed by the reference)
#define NN    50000
#define HH    128
#define TT    4
#define EE    150000
#define G3    384      // 3*H

// ---------------------------------------------------------------------------
// Scratch (no allocations allowed -> __device__ globals)
// ---------------------------------------------------------------------------
__device__ float g_h  [(size_t)NN * HH];   // current hidden state
__device__ float g_inc[(size_t)NN * HH];   // incoming messages (segment sum)
__device__ float g_gx [(size_t)NN * G3];   // input gates
__device__ float g_gh [(size_t)NN * G3];   // hidden gates

// ---------------------------------------------------------------------------
// Message kernel: fused gather -> GEMM -> atomic scatter
//   msgs[t,e,f] = sum_h h[src[t,e],h] * W[t,f,h] + b[t,f]
//   inc[tgt[t,e],f] += msgs[t,e,f]
// Block tile: 128 edges x 128 outputs, K=128, BK=8, 256 threads, 8x8 microtile
// ---------------------------------------------------------------------------
__global__ void __launch_bounds__(256)
msg_kernel(const float* __restrict__ h,
           const int*   __restrict__ edges,   // (T,E,2)
           const float* __restrict__ Wl,      // (T,H,H) for this layer
           const float* __restrict__ bl)      // (T,H)
{
    __shared__ __align__(16) float As[8][128];
    __shared__ __align__(16) float Bs[8][128];
    __shared__ int s_src[128];
    __shared__ int s_tgt[128];

    const int t   = blockIdx.y;
    const int e0  = blockIdx.x * 128;
    const int tid = threadIdx.x;

    if (tid < 128) {
        int e = e0 + tid;
        int s = 0, g = -1;
        if (e < EE) {
            size_t base = ((size_t)t * EE + e) * 2;
            s = edges[base + 0];
            g = edges[base + 1];
        }
        s_src[tid] = s;
        s_tgt[tid] = g;
    }
    __syncthreads();

    const float* W = Wl + (size_t)t * HH * HH;

    const int lr   = tid >> 1;   // 0..127: row within tile for loads
    const int part = tid & 1;    // which float4 of the 8-wide K chunk
    const int ty   = tid >> 4;   // 0..15
    const int tx   = tid & 15;   // 0..15

    float acc[8][8];
    #pragma unroll
    for (int i = 0; i < 8; ++i)
        #pragma unroll
        for (int j = 0; j < 8; ++j) acc[i][j] = 0.0f;

    for (int kt = 0; kt < HH; kt += 8) {
        // Gather A tile: As[k][row] = h[src[row]*128 + kt + k]
        {
            const float* arow = h + (size_t)s_src[lr] * HH + kt + part * 4;
            float4 v = *reinterpret_cast<const float4*>(arow);
            As[part*4+0][lr] = v.x; As[part*4+1][lr] = v.y;
            As[part*4+2][lr] = v.z; As[part*4+3][lr] = v.w;
        }
        // W tile: Bs[k][f] = W[f*128 + kt + k]
        {
            const float* wrow = W + (size_t)lr * HH + kt + part * 4;
            float4 v = *reinterpret_cast<const float4*>(wrow);
            Bs[part*4+0][lr] = v.x; Bs[part*4+1][lr] = v.y;
            Bs[part*4+2][lr] = v.z; Bs[part*4+3][lr] = v.w;
        }
        __syncthreads();

        #pragma unroll
        for (int k = 0; k < 8; ++k) {
            float4 a0 = *reinterpret_cast<const float4*>(&As[k][ty*8]);
            float4 a1 = *reinterpret_cast<const float4*>(&As[k][ty*8+4]);
            float4 b0 = *reinterpret_cast<const float4*>(&Bs[k][tx*8]);
            float4 b1 = *reinterpret_cast<const float4*>(&Bs[k][tx*8+4]);
            float a[8] = {a0.x,a0.y,a0.z,a0.w,a1.x,a1.y,a1.z,a1.w};
            float b[8] = {b0.x,b0.y,b0.z,b0.w,b1.x,b1.y,b1.z,b1.w};
            #pragma unroll
            for (int i = 0; i < 8; ++i)
                #pragma unroll
                for (int j = 0; j < 8; ++j)
                    acc[i][j] = fmaf(a[i], b[j], acc[i][j]);
        }
        __syncthreads();
    }

    // Epilogue: bias + atomic scatter into inc (g_inc)
    float bias[8];
    #pragma unroll
    for (int j = 0; j < 8; ++j) bias[j] = bl[(size_t)t * HH + tx*8 + j];

    #pragma unroll
    for (int i = 0; i < 8; ++i) {
        int row = ty*8 + i;
        int tgt = s_tgt[row];
        if (tgt >= 0) {
            float* dst = g_inc + (size_t)tgt * HH + tx*8;
            #pragma unroll
            for (int j = 0; j < 8; ++j)
                atomicAdd(dst + j, acc[i][j] + bias[j]);
        }
    }
}

// ---------------------------------------------------------------------------
// Gates GEMM: C[m, n] = bias[n] + sum_k a(m,k) * W[n*K + k]
// Logical A = [A0 | A1] (each 128 cols, row-major); A1 may be null if K==128.
// C has row stride 384. Tile 128x128, BK=8.
// ---------------------------------------------------------------------------
__global__ void __launch_bounds__(256)
gemm_gates_kernel(const float* __restrict__ A0,
                  const float* __restrict__ A1,
                  const float* __restrict__ W,
                  const float* __restrict__ bias,
                  float* __restrict__ C,
                  int M, int K)
{
    __shared__ __align__(16) float As[8][128];
    __shared__ __align__(16) float Bs[8][128];

    const int tid  = threadIdx.x;
    const int row0 = blockIdx.x * 128;
    const int col0 = blockIdx.y * 128;

    const int lr   = tid >> 1;
    const int part = tid & 1;
    const int ty   = tid >> 4;
    const int tx   = tid & 15;

    float acc[8][8];
    #pragma unroll
    for (int i = 0; i < 8; ++i)
        #pragma unroll
        for (int j = 0; j < 8; ++j) acc[i][j] = 0.0f;

    for (int kt = 0; kt < K; kt += 8) {
        // A tile (guarded on M)
        {
            int m = row0 + lr;
            const float* src = (kt < 128) ? A0 : A1;
            int kk = (kt < 128) ? kt : (kt - 128);
            float4 v = make_float4(0.f, 0.f, 0.f, 0.f);
            if (m < M)
                v = *reinterpret_cast<const float4*>(src + (size_t)m * HH + kk + part * 4);
            As[part*4+0][lr] = v.x; As[part*4+1][lr] = v.y;
            As[part*4+2][lr] = v.z; As[part*4+3][lr] = v.w;
        }
        // W tile: Bs[k][n] = W[(col0+n)*K + kt + k]   (384 rows, always valid)
        {
            const float* wrow = W + (size_t)(col0 + lr) * K + kt + part * 4;
            float4 v = *reinterpret_cast<const float4*>(wrow);
            Bs[part*4+0][lr] = v.x; Bs[part*4+1][lr] = v.y;
            Bs[part*4+2][lr] = v.z; Bs[part*4+3][lr] = v.w;
        }
        __syncthreads();

        #pragma unroll
        for (int k = 0; k < 8; ++k) {
            float4 a0 = *reinterpret_cast<const float4*>(&As[k][ty*8]);
            float4 a1 = *reinterpret_cast<const float4*>(&As[k][ty*8+4]);
            float4 b0 = *reinterpret_cast<const float4*>(&Bs[k][tx*8]);
            float4 b1 = *reinterpret_cast<const float4*>(&Bs[k][tx*8+4]);
            float a[8] = {a0.x,a0.y,a0.z,a0.w,a1.x,a1.y,a1.z,a1.w};
            float b[8] = {b0.x,b0.y,b0.z,b0.w,b1.x,b1.y,b1.z,b1.w};
            #pragma unroll
            for (int i = 0; i < 8; ++i)
                #pragma unroll
                for (int j = 0; j < 8; ++j)
                    acc[i][j] = fmaf(a[i], b[j], acc[i][j]);
        }
        __syncthreads();
    }

    float bv[8];
    #pragma unroll
    for (int j = 0; j < 8; ++j) bv[j] = bias[col0 + tx*8 + j];

    #pragma unroll
    for (int i = 0; i < 8; ++i) {
        int m = row0 + ty*8 + i;
        if (m < M) {
            float* crow = C + (size_t)m * G3 + col0 + tx*8;
            #pragma unroll
            for (int j = 0; j < 8; ++j) crow[j] = acc[i][j] + bv[j];
        }
    }
}

// ---------------------------------------------------------------------------
// GRU elementwise update (in place on h)
// ---------------------------------------------------------------------------
__global__ void gru_update_kernel(const float* __restrict__ gx,
                                  const float* __restrict__ gh,
                                  float* __restrict__ h)
{
    int idx = blockIdx.x * blockDim.x + threadIdx.x;
    if (idx >= NN * HH) return;
    int m = idx >> 7;
    int n = idx & 127;

    size_t base = (size_t)m * G3 + n;
    float xr = gx[base +   0], xz = gx[base + 128], xn = gx[base + 256];
    float hr = gh[base +   0], hz = gh[base + 128], hn = gh[base + 256];

    float r = 1.0f / (1.0f + expf(-(xr + hr)));
    float z = 1.0f / (1.0f + expf(-(xz + hz)));
    float nv = tanhf(xn + r * hn);
    float hv = h[idx];
    h[idx] = (1.0f - z) * nv + z * hv;
}

// ---------------------------------------------------------------------------
// Launch
// ---------------------------------------------------------------------------
extern "C" void kernel_launch(void* const* d_in, const int* in_sizes, int n_in,
                              void* d_out, int out_size)
{
    const float* x        = (const float*)d_in[0];
    const int*   edges    = (const int*)  d_in[1];
    const float* msg_W    = (const float*)d_in[2];   // (L,T,H,H)
    const float* msg_b    = (const float*)d_in[3];   // (L,T,H)
    const float* g0_Wih   = (const float*)d_in[4];
    const float* g0_Whh   = (const float*)d_in[5];
    const float* g0_bih   = (const float*)d_in[6];
    const float* g0_bhh   = (const float*)d_in[7];
    const float* g1_Wih   = (const float*)d_in[8];   // (384, 256)
    const float* g1_Whh   = (const float*)d_in[9];
    const float* g1_bih   = (const float*)d_in[10];
    const float* g1_bhh   = (const float*)d_in[11];

    float *h_, *inc_, *gx_, *gh_;
    cudaGetSymbolAddress((void**)&h_,   g_h);
    cudaGetSymbolAddress((void**)&inc_, g_inc);
    cudaGetSymbolAddress((void**)&gx_,  g_gx);
    cudaGetSymbolAddress((void**)&gh_,  g_gh);

    const size_t hbytes = (size_t)NN * HH * sizeof(float);

    cudaMemcpyAsync(h_, x, hbytes, cudaMemcpyDeviceToDevice);

    const dim3 msg_grid((EE + 127) / 128, TT);
    const dim3 gemm_grid((NN + 127) / 128, G3 / 128);
    const int  gru_blocks = (NN * HH + 255) / 256;

    // ---- Layer 0: 3 timesteps ----
    for (int s = 0; s < 3; ++s) {
        cudaMemsetAsync(inc_, 0, hbytes);
        msg_kernel<<<msg_grid, 256>>>(h_, edges,
                                      msg_W + (size_t)0 * TT * HH * HH,
                                      msg_b + (size_t)0 * TT * HH);
        gemm_gates_kernel<<<gemm_grid, 256>>>(inc_, nullptr, g0_Wih, g0_bih, gx_, NN, 128);
        gemm_gates_kernel<<<gemm_grid, 256>>>(h_,   nullptr, g0_Whh, g0_bhh, gh_, NN, 128);
        gru_update_kernel<<<gru_blocks, 256>>>(gx_, gh_, h_);
    }

    // ---- Layer 1: 3 timesteps (input = concat[x, inc]) ----
    for (int s = 0; s < 3; ++s) {
        cudaMemsetAsync(inc_, 0, hbytes);
        msg_kernel<<<msg_grid, 256>>>(h_, edges,
                                      msg_W + (size_t)1 * TT * HH * HH,
                                      msg_b + (size_t)1 * TT * HH);
        gemm_gates_kernel<<<gemm_grid, 256>>>(x, inc_, g1_Wih, g1_bih, gx_, NN, 256);
        gemm_gates_kernel<<<gemm_grid, 256>>>(h_, nullptr, g1_Whh, g1_bhh, gh_, NN, 128);
        gru_update_kernel<<<gru_blocks, 256>>>(gx_, gh_, h_);
    }

    cudaMemcpyAsync(d_out, h_, hbytes, cudaMemcpyDeviceToDevice);
}

// round 3
// speedup vs baseline: 1.6220x; 1.6220x over previous
#include <cuda_runtime.h>
#include <cstddef>

// Problem constants (fixed by the reference)
#define NN    50000
#define HH    128
#define TT    4
#define EE    150000
#define G3    384      // 3*H
#define K4    512      // T*H
#define SEGS  (NN*TT)

// ---------------------------------------------------------------------------
// Scratch (no allocations allowed -> __device__ globals)
// ---------------------------------------------------------------------------
__device__ float g_h   [(size_t)NN * HH];   // current hidden state
__device__ float g_S   [(size_t)NN * K4];   // per-(node,type) summed h_src
__device__ float g_inc [(size_t)NN * HH];   // incoming messages
__device__ float g_gx  [(size_t)NN * G3];   // input gates
__device__ float g_gh  [(size_t)NN * G3];   // hidden gates
__device__ float g_gx1c[(size_t)NN * G3];   // precomputed x-part of layer1 gx
__device__ float g_Wcat[2 * HH * K4];       // msg_W rearranged: [l][f][t*128+k]
__device__ int   g_cnt [SEGS];
__device__ int   g_off [SEGS + 1];
__device__ int   g_cur [SEGS];
__device__ int   g_csr [TT * EE];

// ---------------------------------------------------------------------------
// CSR build (edges are identical across all timesteps -> build once/launch)
// ---------------------------------------------------------------------------
__global__ void count_kernel(const int* __restrict__ edges)
{
    int idx = blockIdx.x * blockDim.x + threadIdx.x;
    if (idx >= TT * EE) return;
    int t   = idx / EE;
    int tgt = edges[(size_t)idx * 2 + 1];
    atomicAdd(&g_cnt[tgt * TT + t], 1);
}

// single-block exclusive scan over SEGS entries
__global__ void scan_kernel()
{
    __shared__ int s[1024];
    const int n     = SEGS;
    const int chunk = (n + 1023) / 1024;
    int tid = threadIdx.x;
    int lo  = tid * chunk;
    int hi  = min(lo + chunk, n);

    int sum = 0;
    for (int i = lo; i < hi; ++i) sum += g_cnt[i];
    s[tid] = sum;
    __syncthreads();
    for (int o = 1; o < 1024; o <<= 1) {
        int v = (tid >= o) ? s[tid - o] : 0;
        __syncthreads();
        s[tid] += v;
        __syncthreads();
    }
    int run = (tid == 0) ? 0 : s[tid - 1];
    for (int i = lo; i < hi; ++i) { g_off[i] = run; run += g_cnt[i]; }
    if (tid == 1023) g_off[n] = s[1023];
}

__global__ void fill_kernel(const int* __restrict__ edges)
{
    int idx = blockIdx.x * blockDim.x + threadIdx.x;
    if (idx >= TT * EE) return;
    int t   = idx / EE;
    int src = edges[(size_t)idx * 2 + 0];
    int tgt = edges[(size_t)idx * 2 + 1];
    int seg = tgt * TT + t;
    int pos = atomicAdd(&g_cur[seg], 1);
    g_csr[pos] = src;
}

// Rearrange msg_W (L,T,H,H) -> Wcat[l][f][t*128+k]
__global__ void wcat_kernel(const float* __restrict__ msg_W)
{
    int idx = blockIdx.x * blockDim.x + threadIdx.x;
    if (idx >= 2 * HH * K4) return;
    int l  = idx / (HH * K4);
    int r  = idx % (HH * K4);
    int f  = r / K4;
    int kk = r % K4;
    int t  = kk >> 7;
    int k  = kk & 127;
    g_Wcat[idx] = msg_W[(((size_t)l * TT + t) * HH + f) * HH + k];
}

// ---------------------------------------------------------------------------
// Aggregation: S[n, t*128+f] = sum over incoming edges of type t of h[src][f]
// One block per node, 128 threads (one per feature). No atomics.
// ---------------------------------------------------------------------------
__global__ void __launch_bounds__(128)
agg_kernel(const float* __restrict__ h)
{
    int n = blockIdx.x;
    int f = threadIdx.x;
    #pragma unroll
    for (int t = 0; t < TT; ++t) {
        int b = g_off[n * TT + t];
        int e = g_off[n * TT + t + 1];
        float a = 0.f;
        for (int i = b; i < e; ++i)
            a += __ldg(&h[(size_t)g_csr[i] * HH + f]);
        g_S[(size_t)n * K4 + t * HH + f] = a;
    }
}

// ---------------------------------------------------------------------------
// General GEMM: C[m, col0+n] = opt_bias[n] + opt_Cin[m] + sum_k A[m*lda+k]*W[n*wld+k]
// Tile 128x128, BK=8, 256 threads, 8x8 microtile.
// ---------------------------------------------------------------------------
__global__ void __launch_bounds__(256)
gemm_kernel(const float* __restrict__ A, int lda,
            const float* __restrict__ W, int wld,
            const float* __restrict__ bias,   // may be null
            const float* __restrict__ Cin,    // may be null (stride ldc)
            float* __restrict__ C, int ldc,
            int M, int K)
{
    __shared__ __align__(16) float As[8][128];
    __shared__ __align__(16) float Bs[8][128];

    const int tid  = threadIdx.x;
    const int row0 = blockIdx.x * 128;
    const int col0 = blockIdx.y * 128;

    const int lr   = tid >> 1;
    const int part = tid & 1;
    const int ty   = tid >> 4;
    const int tx   = tid & 15;

    float acc[8][8];
    #pragma unroll
    for (int i = 0; i < 8; ++i)
        #pragma unroll
        for (int j = 0; j < 8; ++j) acc[i][j] = 0.0f;

    for (int kt = 0; kt < K; kt += 8) {
        {
            int m = row0 + lr;
            float4 v = make_float4(0.f, 0.f, 0.f, 0.f);
            if (m < M)
                v = *reinterpret_cast<const float4*>(A + (size_t)m * lda + kt + part * 4);
            As[part*4+0][lr] = v.x; As[part*4+1][lr] = v.y;
            As[part*4+2][lr] = v.z; As[part*4+3][lr] = v.w;
        }
        {
            const float* wrow = W + (size_t)(col0 + lr) * wld + kt + part * 4;
            float4 v = *reinterpret_cast<const float4*>(wrow);
            Bs[part*4+0][lr] = v.x; Bs[part*4+1][lr] = v.y;
            Bs[part*4+2][lr] = v.z; Bs[part*4+3][lr] = v.w;
        }
        __syncthreads();

        #pragma unroll
        for (int k = 0; k < 8; ++k) {
            float4 a0 = *reinterpret_cast<const float4*>(&As[k][ty*8]);
            float4 a1 = *reinterpret_cast<const float4*>(&As[k][ty*8+4]);
            float4 b0 = *reinterpret_cast<const float4*>(&Bs[k][tx*8]);
            float4 b1 = *reinterpret_cast<const float4*>(&Bs[k][tx*8+4]);
            float a[8] = {a0.x,a0.y,a0.z,a0.w,a1.x,a1.y,a1.z,a1.w};
            float b[8] = {b0.x,b0.y,b0.z,b0.w,b1.x,b1.y,b1.z,b1.w};
            #pragma unroll
            for (int i = 0; i < 8; ++i)
                #pragma unroll
                for (int j = 0; j < 8; ++j)
                    acc[i][j] = fmaf(a[i], b[j], acc[i][j]);
        }
        __syncthreads();
    }

    float bv[8];
    #pragma unroll
    for (int j = 0; j < 8; ++j) bv[j] = bias ? bias[col0 + tx*8 + j] : 0.f;

    #pragma unroll
    for (int i = 0; i < 8; ++i) {
        int m = row0 + ty*8 + i;
        if (m < M) {
            float* crow = C + (size_t)m * ldc + col0 + tx*8;
            if (Cin) {
                const float* cin = Cin + (size_t)m * ldc + col0 + tx*8;
                #pragma unroll
                for (int j = 0; j < 8; ++j) crow[j] = acc[i][j] + bv[j] + cin[j];
            } else {
                #pragma unroll
                for (int j = 0; j < 8; ++j) crow[j] = acc[i][j] + bv[j];
            }
        }
    }
}

// ---------------------------------------------------------------------------
// inc GEMM: inc[m,f] = sum_kk S[m,kk]*Wcat[f,kk] + sum_t deg_t[m]*b_l[t,f]
// K=512, 128 output cols (gridDim.y == 1).
// ---------------------------------------------------------------------------
__global__ void __launch_bounds__(256)
gemm_inc_kernel(const float* __restrict__ S,
                const float* __restrict__ Wc,    // [128][512]
                const float* __restrict__ bl,    // (T,H)
                float* __restrict__ inc)
{
    __shared__ __align__(16) float As[8][128];
    __shared__ __align__(16) float Bs[8][128];
    __shared__ float sb[TT * HH];

    const int tid  = threadIdx.x;
    const int row0 = blockIdx.x * 128;

    for (int i = tid; i < TT * HH; i += 256) sb[i] = bl[i];

    const int lr   = tid >> 1;
    const int part = tid & 1;
    const int ty   = tid >> 4;
    const int tx   = tid & 15;

    float acc[8][8];
    #pragma unroll
    for (int i = 0; i < 8; ++i)
        #pragma unroll
        for (int j = 0; j < 8; ++j) acc[i][j] = 0.0f;

    for (int kt = 0; kt < K4; kt += 8) {
        {
            int m = row0 + lr;
            float4 v = make_float4(0.f, 0.f, 0.f, 0.f);
            if (m < NN)
                v = *reinterpret_cast<const float4*>(S + (size_t)m * K4 + kt + part * 4);
            As[part*4+0][lr] = v.x; As[part*4+1][lr] = v.y;
            As[part*4+2][lr] = v.z; As[part*4+3][lr] = v.w;
        }
        {
            const float* wrow = Wc + (size_t)lr * K4 + kt + part * 4;
            float4 v = *reinterpret_cast<const float4*>(wrow);
            Bs[part*4+0][lr] = v.x; Bs[part*4+1][lr] = v.y;
            Bs[part*4+2][lr] = v.z; Bs[part*4+3][lr] = v.w;
        }
        __syncthreads();

        #pragma unroll
        for (int k = 0; k < 8; ++k) {
            float4 a0 = *reinterpret_cast<const float4*>(&As[k][ty*8]);
            float4 a1 = *reinterpret_cast<const float4*>(&As[k][ty*8+4]);
            float4 b0 = *reinterpret_cast<const float4*>(&Bs[k][tx*8]);
            float4 b1 = *reinterpret_cast<const float4*>(&Bs[k][tx*8+4]);
            float a[8] = {a0.x,a0.y,a0.z,a0.w,a1.x,a1.y,a1.z,a1.w};
            float b[8] = {b0.x,b0.y,b0.z,b0.w,b1.x,b1.y,b1.z,b1.w};
            #pragma unroll
            for (int i = 0; i < 8; ++i)
                #pragma unroll
                for (int j = 0; j < 8; ++j)
                    acc[i][j] = fmaf(a[i], b[j], acc[i][j]);
        }
        __syncthreads();
    }

    #pragma unroll
    for (int i = 0; i < 8; ++i) {
        int m = row0 + ty*8 + i;
        if (m < NN) {
            int o0 = g_off[m*TT+0], o1 = g_off[m*TT+1], o2 = g_off[m*TT+2];
            int o3 = g_off[m*TT+3], o4 = g_off[m*TT+4];
            float d0 = (float)(o1-o0), d1 = (float)(o2-o1);
            float d2 = (float)(o3-o2), d3 = (float)(o4-o3);
            float* crow = inc + (size_t)m * HH + tx*8;
            #pragma unroll
            for (int j = 0; j < 8; ++j) {
                int f = tx*8 + j;
                float v = acc[i][j];
                v += d0 * sb[0*HH+f] + d1 * sb[1*HH+f]
                   + d2 * sb[2*HH+f] + d3 * sb[3*HH+f];
                crow[j] = v;
            }
        }
    }
}

// ---------------------------------------------------------------------------
// GRU elementwise update (in place on h)
// ---------------------------------------------------------------------------
__global__ void gru_update_kernel(const float* __restrict__ gx,
                                  const float* __restrict__ gh,
                                  float* __restrict__ h)
{
    int idx = blockIdx.x * blockDim.x + threadIdx.x;
    if (idx >= NN * HH) return;
    int m = idx >> 7;
    int n = idx & 127;

    size_t base = (size_t)m * G3 + n;
    float xr = gx[base +   0], xz = gx[base + 128], xn = gx[base + 256];
    float hr = gh[base +   0], hz = gh[base + 128], hn = gh[base + 256];

    float r = 1.0f / (1.0f + expf(-(xr + hr)));
    float z = 1.0f / (1.0f + expf(-(xz + hz)));
    float nv = tanhf(xn + r * hn);
    float hv = h[idx];
    h[idx] = (1.0f - z) * nv + z * hv;
}

// ---------------------------------------------------------------------------
// Launch
// ---------------------------------------------------------------------------
extern "C" void kernel_launch(void* const* d_in, const int* in_sizes, int n_in,
                              void* d_out, int out_size)
{
    const float* x        = (const float*)d_in[0];
    const int*   edges    = (const int*)  d_in[1];
    const float* msg_W    = (const float*)d_in[2];   // (L,T,H,H)
    const float* msg_b    = (const float*)d_in[3];   // (L,T,H)
    const float* g0_Wih   = (const float*)d_in[4];
    const float* g0_Whh   = (const float*)d_in[5];
    const float* g0_bih   = (const float*)d_in[6];
    const float* g0_bhh   = (const float*)d_in[7];
    const float* g1_Wih   = (const float*)d_in[8];   // (384, 256)
    const float* g1_Whh   = (const float*)d_in[9];
    const float* g1_bih   = (const float*)d_in[10];
    const float* g1_bhh   = (const float*)d_in[11];

    float *h_, *S_, *inc_, *gx_, *gh_, *gx1c_, *Wcat_;
    int *cnt_, *off_, *cur_;
    cudaGetSymbolAddress((void**)&h_,    g_h);
    cudaGetSymbolAddress((void**)&S_,    g_S);
    cudaGetSymbolAddress((void**)&inc_,  g_inc);
    cudaGetSymbolAddress((void**)&gx_,   g_gx);
    cudaGetSymbolAddress((void**)&gh_,   g_gh);
    cudaGetSymbolAddress((void**)&gx1c_, g_gx1c);
    cudaGetSymbolAddress((void**)&Wcat_, g_Wcat);
    cudaGetSymbolAddress((void**)&cnt_,  g_cnt);
    cudaGetSymbolAddress((void**)&off_,  g_off);
    cudaGetSymbolAddress((void**)&cur_,  g_cur);

    const size_t hbytes = (size_t)NN * HH * sizeof(float);

    cudaMemcpyAsync(h_, x, hbytes, cudaMemcpyDeviceToDevice);

    // --- CSR build (once; edges constant across timesteps) ---
    cudaMemsetAsync(cnt_, 0, SEGS * sizeof(int));
    count_kernel<<<(TT*EE + 255)/256, 256>>>(edges);
    scan_kernel<<<1, 1024>>>();
    cudaMemcpyAsync(cur_, off_, SEGS * sizeof(int), cudaMemcpyDeviceToDevice);
    fill_kernel<<<(TT*EE + 255)/256, 256>>>(edges);

    // --- Weight rearrange + layer1 constant gx part ---
    wcat_kernel<<<(2*HH*K4 + 255)/256, 256>>>(msg_W);

    const dim3 gate_grid((NN + 127)/128, G3/128);
    const dim3 inc_grid ((NN + 127)/128, 1);
    const int  gru_blocks = (NN * HH + 255) / 256;

    // gx1c = x @ Wih1[:, :128]^T + bih1  (constant across layer-1 steps)
    gemm_kernel<<<gate_grid, 256>>>(x, HH, g1_Wih, 2*HH, g1_bih, nullptr,
                                    gx1c_, G3, NN, HH);

    // ---- Layer 0: 3 timesteps ----
    for (int s = 0; s < 3; ++s) {
        agg_kernel<<<NN, HH>>>(h_);
        gemm_inc_kernel<<<inc_grid, 256>>>(S_, Wcat_ + 0*HH*K4,
                                           msg_b + (size_t)0*TT*HH, inc_);
        gemm_kernel<<<gate_grid, 256>>>(inc_, HH, g0_Wih, HH, g0_bih, nullptr,
                                        gx_, G3, NN, HH);
        gemm_kernel<<<gate_grid, 256>>>(h_, HH, g0_Whh, HH, g0_bhh, nullptr,
                                        gh_, G3, NN, HH);
        gru_update_kernel<<<gru_blocks, 256>>>(gx_, gh_, h_);
    }

    // ---- Layer 1: 3 timesteps ----
    for (int s = 0; s < 3; ++s) {
        agg_kernel<<<NN, HH>>>(h_);
        gemm_inc_kernel<<<inc_grid, 256>>>(S_, Wcat_ + 1*HH*K4,
                                           msg_b + (size_t)1*TT*HH, inc_);
        // gx = gx1c + inc @ Wih1[:, 128:]^T
        gemm_kernel<<<gate_grid, 256>>>(inc_, HH, g1_Wih + HH, 2*HH, nullptr, gx1c_,
                                        gx_, G3, NN, HH);
        gemm_kernel<<<gate_grid, 256>>>(h_, HH, g1_Whh, HH, g1_bhh, nullptr,
                                        gh_, G3, NN, HH);
        gru_update_kernel<<<gru_blocks, 256>>>(gx_, gh_, h_);
    }

    cudaMemcpyAsync(d_out, h_, hbytes, cudaMemcpyDeviceToDevice);
}

// round 4
// speedup vs baseline: 2.7275x; 1.6816x over previous
#include <cuda_runtime.h>
#include <cstdint>
#include <cstddef>

// Problem constants (fixed by the reference)
#define NN    50000
#define HH    128
#define TT    4
#define EE    150000
#define G3    384      // 3*H
#define K4    512      // T*H
#define SEGS  (NN*TT)

// ---------------------------------------------------------------------------
// Scratch (no allocations allowed -> __device__ globals)
// ---------------------------------------------------------------------------
__device__ float g_h   [(size_t)NN * HH];
__device__ float g_S   [(size_t)NN * K4];
__device__ float g_inc [(size_t)NN * HH];
__device__ float g_gx  [(size_t)NN * G3];
__device__ float g_gh  [(size_t)NN * G3];
__device__ float g_gx1c[(size_t)NN * G3];
__device__ float g_Wcat[2 * HH * K4];
__device__ int   g_cnt [SEGS];
__device__ int   g_off [SEGS + 1];
__device__ int   g_cur [SEGS];
__device__ int   g_csr [TT * EE];

// ---------------------------------------------------------------------------
// CSR build (edges identical across timesteps -> build once per launch)
// ---------------------------------------------------------------------------
__global__ void count_kernel(const int* __restrict__ edges)
{
    int idx = blockIdx.x * blockDim.x + threadIdx.x;
    if (idx >= TT * EE) return;
    int t   = idx / EE;
    int tgt = edges[(size_t)idx * 2 + 1];
    atomicAdd(&g_cnt[tgt * TT + t], 1);
}

__global__ void scan_kernel()
{
    __shared__ int s[1024];
    const int n     = SEGS;
    const int chunk = (n + 1023) / 1024;
    int tid = threadIdx.x;
    int lo  = tid * chunk;
    int hi  = min(lo + chunk, n);

    int sum = 0;
    for (int i = lo; i < hi; ++i) sum += g_cnt[i];
    s[tid] = sum;
    __syncthreads();
    for (int o = 1; o < 1024; o <<= 1) {
        int v = (tid >= o) ? s[tid - o] : 0;
        __syncthreads();
        s[tid] += v;
        __syncthreads();
    }
    int run = (tid == 0) ? 0 : s[tid - 1];
    for (int i = lo; i < hi; ++i) { g_off[i] = run; run += g_cnt[i]; }
    if (tid == 1023) g_off[n] = s[1023];
}

__global__ void fill_kernel(const int* __restrict__ edges)
{
    int idx = blockIdx.x * blockDim.x + threadIdx.x;
    if (idx >= TT * EE) return;
    int t   = idx / EE;
    int src = edges[(size_t)idx * 2 + 0];
    int tgt = edges[(size_t)idx * 2 + 1];
    int seg = tgt * TT + t;
    int pos = atomicAdd(&g_cur[seg], 1);
    g_csr[pos] = src;
}

// Rearrange msg_W (L,T,H,H) -> Wcat[l][f][t*128+k]
__global__ void wcat_kernel(const float* __restrict__ msg_W)
{
    int idx = blockIdx.x * blockDim.x + threadIdx.x;
    if (idx >= 2 * HH * K4) return;
    int l  = idx / (HH * K4);
    int r  = idx % (HH * K4);
    int f  = r / K4;
    int kk = r % K4;
    int t  = kk >> 7;
    int k  = kk & 127;
    g_Wcat[idx] = msg_W[(((size_t)l * TT + t) * HH + f) * HH + k];
}

// ---------------------------------------------------------------------------
// Aggregation: S[n, t*128+f] = sum over incoming type-t edges of h[src][f]
// ---------------------------------------------------------------------------
__global__ void __launch_bounds__(128)
agg_kernel(const float* __restrict__ h)
{
    int n = blockIdx.x;
    int f = threadIdx.x;
    #pragma unroll
    for (int t = 0; t < TT; ++t) {
        int b = g_off[n * TT + t];
        int e = g_off[n * TT + t + 1];
        float a = 0.f;
        for (int i = b; i < e; ++i)
            a += __ldg(&h[(size_t)g_csr[i] * HH + f]);
        g_S[(size_t)n * K4 + t * HH + f] = a;
    }
}

// ---------------------------------------------------------------------------
// tf32 tensor-core GEMM
//   C[m, col0+n] = epilogue( sum_k A[m*lda+k] * W[(col0+n)*wld+k] )
//   MODE 0: + bias[col0+n] (may be null) + Cin[m*ldc+col0+n] (may be null)
//   MODE 1: + sum_t deg_t[m] * bl[t*128+f]   (inc epilogue, col0 == 0)
// Block: 128x128 tile, BK=32, 256 threads (8 warps, 4x2 of 32x64 warp tiles)
// ---------------------------------------------------------------------------
__device__ __forceinline__ float to_tf32(float x)
{
    uint32_t u;
    asm("cvt.rna.tf32.f32 %0, %1;" : "=r"(u) : "f"(x));
    return __uint_as_float(u);
}

__device__ __forceinline__ void mma_tf32(float* c, const uint32_t* a, const uint32_t* b)
{
    asm volatile(
        "mma.sync.aligned.m16n8k8.row.col.f32.tf32.tf32.f32 "
        "{%0,%1,%2,%3}, {%4,%5,%6,%7}, {%8,%9}, {%0,%1,%2,%3};"
        : "+f"(c[0]), "+f"(c[1]), "+f"(c[2]), "+f"(c[3])
        : "r"(a[0]), "r"(a[1]), "r"(a[2]), "r"(a[3]),
          "r"(b[0]), "r"(b[1]));
}

#define SSTR 36   // padded shared stride (words) for BK=32

template<int MODE>
__global__ void __launch_bounds__(256)
gemm_tf32(const float* __restrict__ A, int lda,
          const float* __restrict__ W, int wld,
          const float* __restrict__ bias,
          const float* __restrict__ Cin,
          float* __restrict__ C, int ldc,
          int M, int K)
{
    __shared__ float As[128 * SSTR];
    __shared__ float Bs[128 * SSTR];
    __shared__ float sb[512];

    const int tid  = threadIdx.x;
    const int lane = tid & 31;
    const int warp = tid >> 5;
    const int wm   = warp & 3;          // 0..3 -> m offset wm*32
    const int wn   = warp >> 2;         // 0..1 -> n offset wn*64
    const int row0 = blockIdx.x * 128;
    const int col0 = blockIdx.y * 128;

    if (MODE == 1)
        for (int i = tid; i < 512; i += 256) sb[i] = bias[i];

    float acc[2][8][4];
    #pragma unroll
    for (int mi = 0; mi < 2; ++mi)
        #pragma unroll
        for (int ni = 0; ni < 8; ++ni)
            #pragma unroll
            for (int q = 0; q < 4; ++q) acc[mi][ni][q] = 0.f;

    const int gr = lane >> 2;   // 0..7
    const int gc = lane & 3;    // 0..3

    for (int kt = 0; kt < K; kt += 32) {
        // ---- global -> shared (with tf32 rounding) ----
        #pragma unroll
        for (int i = 0; i < 4; ++i) {
            int idx = tid + i * 256;      // 0..1023
            int r   = idx >> 3;           // 0..127
            int c   = (idx & 7) << 2;     // 0,4,...,28
            float4 v = make_float4(0.f, 0.f, 0.f, 0.f);
            if (row0 + r < M)
                v = *reinterpret_cast<const float4*>(A + (size_t)(row0 + r) * lda + kt + c);
            v.x = to_tf32(v.x); v.y = to_tf32(v.y);
            v.z = to_tf32(v.z); v.w = to_tf32(v.w);
            *reinterpret_cast<float4*>(As + r * SSTR + c) = v;

            float4 w = *reinterpret_cast<const float4*>(W + (size_t)(col0 + r) * wld + kt + c);
            w.x = to_tf32(w.x); w.y = to_tf32(w.y);
            w.z = to_tf32(w.z); w.w = to_tf32(w.w);
            *reinterpret_cast<float4*>(Bs + r * SSTR + c) = w;
        }
        __syncthreads();

        // ---- mma mainloop over 4 x k8 ----
        #pragma unroll
        for (int kq = 0; kq < 4; ++kq) {
            const int kk = kq * 8;
            uint32_t a[2][4];
            #pragma unroll
            for (int mi = 0; mi < 2; ++mi) {
                int am = wm * 32 + mi * 16;
                a[mi][0] = __float_as_uint(As[(am + gr)     * SSTR + kk + gc]);
                a[mi][1] = __float_as_uint(As[(am + gr + 8) * SSTR + kk + gc]);
                a[mi][2] = __float_as_uint(As[(am + gr)     * SSTR + kk + gc + 4]);
                a[mi][3] = __float_as_uint(As[(am + gr + 8) * SSTR + kk + gc + 4]);
            }
            #pragma unroll
            for (int ni = 0; ni < 8; ++ni) {
                int bn = wn * 64 + ni * 8;
                uint32_t b[2];
                b[0] = __float_as_uint(Bs[(bn + gr) * SSTR + kk + gc]);
                b[1] = __float_as_uint(Bs[(bn + gr) * SSTR + kk + gc + 4]);
                mma_tf32(acc[0][ni], a[0], b);
                mma_tf32(acc[1][ni], a[1], b);
            }
        }
        __syncthreads();
    }

    // ---- epilogue ----
    #pragma unroll
    for (int mi = 0; mi < 2; ++mi) {
        const int rbase = row0 + wm * 32 + mi * 16 + gr;
        float dg[2][4];
        if (MODE == 1) {
            #pragma unroll
            for (int hh = 0; hh < 2; ++hh) {
                int r = rbase + hh * 8;
                if (r < M) {
                    int o0 = g_off[r*4+0], o1 = g_off[r*4+1], o2 = g_off[r*4+2];
                    int o3 = g_off[r*4+3], o4 = g_off[r*4+4];
                    dg[hh][0] = (float)(o1 - o0); dg[hh][1] = (float)(o2 - o1);
                    dg[hh][2] = (float)(o3 - o2); dg[hh][3] = (float)(o4 - o3);
                }
            }
        }
        #pragma unroll
        for (int ni = 0; ni < 8; ++ni) {
            const int cc = col0 + wn * 64 + ni * 8 + gc * 2;
            #pragma unroll
            for (int hh = 0; hh < 2; ++hh) {
                int r = rbase + hh * 8;
                if (r < M) {
                    float v0 = acc[mi][ni][hh * 2 + 0];
                    float v1 = acc[mi][ni][hh * 2 + 1];
                    if (MODE == 0) {
                        if (bias) { v0 += bias[cc]; v1 += bias[cc + 1]; }
                        if (Cin) {
                            const float* ci = Cin + (size_t)r * ldc + cc;
                            v0 += ci[0]; v1 += ci[1];
                        }
                    } else {
                        int f = cc;   // col0 == 0 for inc
                        v0 += dg[hh][0]*sb[f]     + dg[hh][1]*sb[128+f]
                            + dg[hh][2]*sb[256+f] + dg[hh][3]*sb[384+f];
                        v1 += dg[hh][0]*sb[f+1]     + dg[hh][1]*sb[128+f+1]
                            + dg[hh][2]*sb[256+f+1] + dg[hh][3]*sb[384+f+1];
                    }
                    *reinterpret_cast<float2*>(C + (size_t)r * ldc + cc) = make_float2(v0, v1);
                }
            }
        }
    }
}

// ---------------------------------------------------------------------------
// GRU elementwise update (in place on h)
// ---------------------------------------------------------------------------
__global__ void gru_update_kernel(const float* __restrict__ gx,
                                  const float* __restrict__ gh,
                                  float* __restrict__ h)
{
    int idx = blockIdx.x * blockDim.x + threadIdx.x;
    if (idx >= NN * HH) return;
    int m = idx >> 7;
    int n = idx & 127;

    size_t base = (size_t)m * G3 + n;
    float xr = gx[base +   0], xz = gx[base + 128], xn = gx[base + 256];
    float hr = gh[base +   0], hz = gh[base + 128], hn = gh[base + 256];

    float r = 1.0f / (1.0f + expf(-(xr + hr)));
    float z = 1.0f / (1.0f + expf(-(xz + hz)));
    float nv = tanhf(xn + r * hn);
    float hv = h[idx];
    h[idx] = (1.0f - z) * nv + z * hv;
}

// ---------------------------------------------------------------------------
// Launch
// ---------------------------------------------------------------------------
extern "C" void kernel_launch(void* const* d_in, const int* in_sizes, int n_in,
                              void* d_out, int out_size)
{
    const float* x        = (const float*)d_in[0];
    const int*   edges    = (const int*)  d_in[1];
    const float* msg_W    = (const float*)d_in[2];
    const float* msg_b    = (const float*)d_in[3];
    const float* g0_Wih   = (const float*)d_in[4];
    const float* g0_Whh   = (const float*)d_in[5];
    const float* g0_bih   = (const float*)d_in[6];
    const float* g0_bhh   = (const float*)d_in[7];
    const float* g1_Wih   = (const float*)d_in[8];   // (384, 256)
    const float* g1_Whh   = (const float*)d_in[9];
    const float* g1_bih   = (const float*)d_in[10];
    const float* g1_bhh   = (const float*)d_in[11];

    float *h_, *S_, *inc_, *gx_, *gh_, *gx1c_, *Wcat_;
    int *cnt_, *off_, *cur_;
    cudaGetSymbolAddress((void**)&h_,    g_h);
    cudaGetSymbolAddress((void**)&S_,    g_S);
    cudaGetSymbolAddress((void**)&inc_,  g_inc);
    cudaGetSymbolAddress((void**)&gx_,   g_gx);
    cudaGetSymbolAddress((void**)&gh_,   g_gh);
    cudaGetSymbolAddress((void**)&gx1c_, g_gx1c);
    cudaGetSymbolAddress((void**)&Wcat_, g_Wcat);
    cudaGetSymbolAddress((void**)&cnt_,  g_cnt);
    cudaGetSymbolAddress((void**)&off_,  g_off);
    cudaGetSymbolAddress((void**)&cur_,  g_cur);

    const size_t hbytes = (size_t)NN * HH * sizeof(float);

    cudaMemcpyAsync(h_, x, hbytes, cudaMemcpyDeviceToDevice);

    // --- CSR build ---
    cudaMemsetAsync(cnt_, 0, SEGS * sizeof(int));
    count_kernel<<<(TT*EE + 255)/256, 256>>>(edges);
    scan_kernel<<<1, 1024>>>();
    cudaMemcpyAsync(cur_, off_, SEGS * sizeof(int), cudaMemcpyDeviceToDevice);
    fill_kernel<<<(TT*EE + 255)/256, 256>>>(edges);

    // --- Weight rearrange ---
    wcat_kernel<<<(2*HH*K4 + 255)/256, 256>>>(msg_W);

    const dim3 gate_grid((NN + 127)/128, G3/128);
    const dim3 inc_grid ((NN + 127)/128, 1);
    const int  gru_blocks = (NN * HH + 255) / 256;

    // gx1c = x @ Wih1[:, :128]^T + bih1  (constant across layer-1 steps)
    gemm_tf32<0><<<gate_grid, 256>>>(x, HH, g1_Wih, 2*HH, g1_bih, nullptr,
                                     gx1c_, G3, NN, HH);

    // ---- Layer 0: 3 timesteps ----
    for (int s = 0; s < 3; ++s) {
        agg_kernel<<<NN, HH>>>(h_);
        gemm_tf32<1><<<inc_grid, 256>>>(S_, K4, Wcat_ + 0*HH*K4, K4,
                                        msg_b + (size_t)0*TT*HH, nullptr,
                                        inc_, HH, NN, K4);
        gemm_tf32<0><<<gate_grid, 256>>>(inc_, HH, g0_Wih, HH, g0_bih, nullptr,
                                         gx_, G3, NN, HH);
        gemm_tf32<0><<<gate_grid, 256>>>(h_, HH, g0_Whh, HH, g0_bhh, nullptr,
                                         gh_, G3, NN, HH);
        gru_update_kernel<<<gru_blocks, 256>>>(gx_, gh_, h_);
    }

    // ---- Layer 1: 3 timesteps ----
    for (int s = 0; s < 3; ++s) {
        agg_kernel<<<NN, HH>>>(h_);
        gemm_tf32<1><<<inc_grid, 256>>>(S_, K4, Wcat_ + 1*HH*K4, K4,
                                        msg_b + (size_t)1*TT*HH, nullptr,
                                        inc_, HH, NN, K4);
        gemm_tf32<0><<<gate_grid, 256>>>(inc_, HH, g1_Wih + HH, 2*HH, nullptr, gx1c_,
                                         gx_, G3, NN, HH);
        gemm_tf32<0><<<gate_grid, 256>>>(h_, HH, g1_Whh, HH, g1_bhh, nullptr,
                                         gh_, G3, NN, HH);
        gru_update_kernel<<<gru_blocks, 256>>>(gx_, gh_, h_);
    }

    cudaMemcpyAsync(d_out, h_, hbytes, cudaMemcpyDeviceToDevice);
}